// round 1
// baseline (speedup 1.0000x reference)
#include <cuda_runtime.h>
#include <float.h>
#include <cstdint>

#define BB   16
#define NPTS 2048
#define BN   (BB * NPTS)
#define KNN  20
#define EPSBN 1e-5f
#define SLOPE 0.2f

// ---------------- scratch (device globals; no allocation allowed) ----------------
__device__ float g_dist[(size_t)BB * NPTS * NPTS];   // 268 MB neg-distance matrix
__device__ float g_xx[BN];
__device__ int   g_idx[BN * KNN];
__device__ float g_x1[BN * 64];
__device__ float g_x2[BN * 64];
__device__ float g_x3[BN * 128];
__device__ float g_x4[BN * 256];
__device__ float g_cat[(size_t)BN * 512];
__device__ float g_ac[(size_t)BN * 512];    // [A | Cc] per edge layer
__device__ float g_y[(size_t)BN * 512];     // conv5 pre-BN
__device__ float g_mx[(size_t)BN * 256];
__device__ float g_mn[(size_t)BN * 256];
__device__ float g_wt[512 * 128];           // transformed weights [2Cout, Cin]
__device__ float g_sum[512];
__device__ float g_sq[512];
__device__ float g_p5max[BB * 16 * 512];
__device__ float g_p5min[BB * 16 * 512];
__device__ float g_z[BB * 512];

// ---------------- kernels ----------------

__global__ void k_zero_sums() {
    g_sum[threadIdx.x] = 0.f;
    g_sq[threadIdx.x]  = 0.f;
}

__global__ void k_sqnorm(const float* __restrict__ X, int C) {
    int i = blockIdx.x * blockDim.x + threadIdx.x;
    if (i >= BN) return;
    const float* row = X + (size_t)i * C;
    float s = 0.f;
    for (int c = 0; c < C; c++) s += row[c] * row[c];
    g_xx[i] = s;
}

// neg_dist[b,i,j] = 2*<x_i,x_j> - |x_i|^2 - |x_j|^2 ; 64x64 tile, 4x4 micro
__global__ void k_dist(const float* __restrict__ X, int C) {
    int b = blockIdx.z;
    const float* Xb  = X + (size_t)b * NPTS * C;
    const float* xxb = g_xx + b * NPTS;
    float* Db = g_dist + (size_t)b * NPTS * NPTS;

    __shared__ float As[16][64];
    __shared__ float Bs[16][64];
    int tid = threadIdx.x;
    int tx = tid & 15, ty = tid >> 4;
    int bi = blockIdx.y * 64, bj = blockIdx.x * 64;

    float acc[4][4] = {};
    for (int k0 = 0; k0 < C; k0 += 16) {
#pragma unroll
        for (int r = 0; r < 4; r++) {
            int i = tid + r * 256;
            int m = i & 63, kk = i >> 6;
            int gk = k0 + kk;
            As[kk][m] = (gk < C) ? Xb[(size_t)(bi + m) * C + gk] : 0.f;
            Bs[kk][m] = (gk < C) ? Xb[(size_t)(bj + m) * C + gk] : 0.f;
        }
        __syncthreads();
#pragma unroll
        for (int kk = 0; kk < 16; kk++) {
            float a[4], bv[4];
#pragma unroll
            for (int u = 0; u < 4; u++) { a[u] = As[kk][ty * 4 + u]; bv[u] = Bs[kk][tx * 4 + u]; }
#pragma unroll
            for (int u = 0; u < 4; u++)
#pragma unroll
                for (int v = 0; v < 4; v++) acc[u][v] += a[u] * bv[v];
        }
        __syncthreads();
    }
#pragma unroll
    for (int u = 0; u < 4; u++) {
        int i = bi + ty * 4 + u;
        float xi = xxb[i];
#pragma unroll
        for (int v = 0; v < 4; v++) {
            int j = bj + tx * 4 + v;
            Db[(size_t)i * NPTS + j] = 2.f * acc[u][v] - xi - xxb[j];
        }
    }
}

// warp per row: top-20 (set semantics only; order irrelevant downstream)
__global__ void k_topk() {
    int gw   = (blockIdx.x * blockDim.x + threadIdx.x) >> 5;
    int lane = threadIdx.x & 31;
    if (gw >= BN) return;
    const float* row = g_dist + (size_t)gw * NPTS;

    float v[KNN]; int id[KNN];
#pragma unroll
    for (int t = 0; t < KNN; t++) { v[t] = -FLT_MAX; id[t] = -1; }

    for (int j = lane; j < NPTS; j += 32) {
        float d = row[j];
        if (d > v[KNN - 1]) {
            int pos = KNN - 1;
            while (pos > 0 && v[pos - 1] < d) {
                v[pos] = v[pos - 1]; id[pos] = id[pos - 1]; pos--;
            }
            v[pos] = d; id[pos] = j;
        }
    }
    // merge 32 sorted lists: 20 rounds of warp-argmax over heads
    int p = 0;
    for (int t = 0; t < KNN; t++) {
        float bh = (p < KNN) ? v[p] : -FLT_MAX;
        int   bl = lane;
        for (int off = 16; off > 0; off >>= 1) {
            float oh = __shfl_down_sync(0xffffffffu, bh, off);
            int   ol = __shfl_down_sync(0xffffffffu, bl, off);
            if (oh > bh) { bh = oh; bl = ol; }
        }
        bl = __shfl_sync(0xffffffffu, bl, 0);
        int hid  = (p < KNN) ? id[p] : -1;
        int widx = __shfl_sync(0xffffffffu, hid, bl);
        if (lane == 0) g_idx[gw * KNN + t] = widx;
        if (lane == bl) p++;
    }
}

// wt[co] = W_d ; wt[Cout+co] = W_c - W_d
__global__ void k_transform_w(const float* __restrict__ w, float* __restrict__ wt,
                              int Cout, int Cin) {
    int i = blockIdx.x * blockDim.x + threadIdx.x;
    if (i >= Cout * Cin) return;
    int co = i / Cin, ci = i % Cin;
    float wd = w[co * 2 * Cin + ci];
    float wc = w[co * 2 * Cin + Cin + ci];
    wt[co * Cin + ci] = wd;
    wt[(Cout + co) * Cin + ci] = wc - wd;
}

// C[m,n] = sum_k A[m,k] * W[n,k]   (M, Ncols multiples of 64)
__global__ void k_gemm_nt(const float* __restrict__ A, const float* __restrict__ W,
                          float* __restrict__ Cm, int M, int Ncols, int Kd) {
    __shared__ float As[16][64];
    __shared__ float Ws[16][64];
    int tid = threadIdx.x;
    int tx = tid & 15, ty = tid >> 4;
    int bm = blockIdx.y * 64, bn = blockIdx.x * 64;

    float acc[4][4] = {};
    for (int k0 = 0; k0 < Kd; k0 += 16) {
#pragma unroll
        for (int r = 0; r < 4; r++) {
            int i = tid + r * 256;
            int m = i & 63, kk = i >> 6;
            int gk = k0 + kk;
            As[kk][m] = (gk < Kd) ? A[(size_t)(bm + m) * Kd + gk] : 0.f;
            Ws[kk][m] = (gk < Kd) ? W[(size_t)(bn + m) * Kd + gk] : 0.f;
        }
        __syncthreads();
#pragma unroll
        for (int kk = 0; kk < 16; kk++) {
            float a[4], wv[4];
#pragma unroll
            for (int u = 0; u < 4; u++) { a[u] = As[kk][ty * 4 + u]; wv[u] = Ws[kk][tx * 4 + u]; }
#pragma unroll
            for (int u = 0; u < 4; u++)
#pragma unroll
                for (int v = 0; v < 4; v++) acc[u][v] += a[u] * wv[v];
        }
        __syncthreads();
    }
#pragma unroll
    for (int u = 0; u < 4; u++)
#pragma unroll
        for (int v = 0; v < 4; v++)
            Cm[(size_t)(bm + ty * 4 + u) * Ncols + bn + tx * 4 + v] = acc[u][v];
}

// per point: gather neighbors' A rows, y = A[idx]+Cc; track max/min over k + channel stats
__global__ void k_edge_pool(const float* __restrict__ AC, int Cout) {
    int bn = blockIdx.x;                 // b*NPTS + n
    __shared__ int sidx[KNN];
    if (threadIdx.x < KNN) sidx[threadIdx.x] = g_idx[bn * KNN + threadIdx.x];
    __syncthreads();
    int b = bn / NPTS;
    const float* ACb = AC + (size_t)b * NPTS * 2 * Cout;
    int co = threadIdx.x;                // blockDim == Cout
    float cc = AC[(size_t)bn * 2 * Cout + Cout + co];
    float vmax = -FLT_MAX, vmin = FLT_MAX, s = 0.f, s2 = 0.f;
#pragma unroll
    for (int kk = 0; kk < KNN; kk++) {
        float y = ACb[(size_t)sidx[kk] * 2 * Cout + co] + cc;
        vmax = fmaxf(vmax, y); vmin = fminf(vmin, y);
        s += y; s2 += y * y;
    }
    g_mx[(size_t)bn * Cout + co] = vmax;
    g_mn[(size_t)bn * Cout + co] = vmin;
    atomicAdd(&g_sum[co], s);
    atomicAdd(&g_sq[co], s2);
}

__global__ void k_edge_fin(const float* __restrict__ gamma, const float* __restrict__ beta,
                           float* __restrict__ Xout, int Cout) {
    int i = blockIdx.x * blockDim.x + threadIdx.x;
    if (i >= BN * Cout) return;
    int co = i % Cout;
    float cnt  = (float)BN * (float)KNN;
    float mean = g_sum[co] / cnt;
    float var  = g_sq[co] / cnt - mean * mean;
    float sc   = gamma[co] * rsqrtf(var + EPSBN);
    float m    = (sc >= 0.f) ? g_mx[i] : g_mn[i];
    float v    = (m - mean) * sc + beta[co];
    Xout[i] = (v > 0.f) ? v : SLOPE * v;
}

__global__ void k_cat() {
    int i = blockIdx.x * blockDim.x + threadIdx.x;
    if (i >= BN * 512) return;
    int n = i >> 9, c = i & 511;
    float v;
    if      (c < 64)  v = g_x1[n * 64 + c];
    else if (c < 128) v = g_x2[n * 64 + (c - 64)];
    else if (c < 256) v = g_x3[(size_t)n * 128 + (c - 128)];
    else              v = g_x4[(size_t)n * 256 + (c - 256)];
    g_cat[i] = v;
}

__global__ void k_pool5_partial() {
    int b = blockIdx.y, chunk = blockIdx.x;   // 16 chunks of 128 rows
    int c = threadIdx.x;                      // 512 threads
    float mx = -FLT_MAX, mn = FLT_MAX, s = 0.f, s2 = 0.f;
    int r0 = chunk * 128;
    for (int r = r0; r < r0 + 128; r++) {
        float v = g_y[((size_t)b * NPTS + r) * 512 + c];
        mx = fmaxf(mx, v); mn = fminf(mn, v);
        s += v; s2 += v * v;
    }
    g_p5max[(b * 16 + chunk) * 512 + c] = mx;
    g_p5min[(b * 16 + chunk) * 512 + c] = mn;
    atomicAdd(&g_sum[c], s);
    atomicAdd(&g_sq[c], s2);
}

__global__ void k_pool5_fin(const float* __restrict__ gamma, const float* __restrict__ beta) {
    int b = blockIdx.x, c = threadIdx.x;
    float cnt  = (float)BN;
    float mean = g_sum[c] / cnt;
    float var  = g_sq[c] / cnt - mean * mean;
    float sc   = gamma[c] * rsqrtf(var + EPSBN);
    float mx = -FLT_MAX, mn = FLT_MAX;
    for (int t = 0; t < 16; t++) {
        mx = fmaxf(mx, g_p5max[(b * 16 + t) * 512 + c]);
        mn = fminf(mn, g_p5min[(b * 16 + t) * 512 + c]);
    }
    float m = (sc >= 0.f) ? mx : mn;
    float v = (m - mean) * sc + beta[c];
    g_z[b * 512 + c] = (v > 0.f) ? v : SLOPE * v;
}

__global__ void k_embed(const float* __restrict__ we, float* __restrict__ out) {
    int b = blockIdx.x, f = threadIdx.x;      // 128 threads
    const float* z  = g_z + b * 512;
    const float* wr = we + f * 512;
    float s = 0.f;
    for (int c = 0; c < 512; c++) s += z[c] * wr[c];
    out[b * 128 + f] = s;
}

// ---------------- host ----------------

static void edge_layer(const float* Xin, int Cin,
                       const float* w, const float* gamma, const float* beta,
                       int Cout, float* Xout, float* p_wt, float* p_ac) {
    // kNN on Xin
    k_sqnorm<<<BN / 256, 256>>>(Xin, Cin);
    dim3 dg(NPTS / 64, NPTS / 64, BB);
    k_dist<<<dg, 256>>>(Xin, Cin);
    k_topk<<<BN / 4, 128>>>();
    // transformed-weight GEMM: [A | Cc]
    int tw = Cout * Cin;
    k_transform_w<<<(tw + 255) / 256, 256>>>(w, p_wt, Cout, Cin);
    k_gemm_nt<<<dim3(2 * Cout / 64, BN / 64), 256>>>(Xin, p_wt, p_ac, BN, 2 * Cout, Cin);
    // pool + BN stats + finalize
    k_zero_sums<<<1, 512>>>();
    k_edge_pool<<<BN, Cout>>>(p_ac, Cout);
    k_edge_fin<<<(BN * Cout + 255) / 256, 256>>>(gamma, beta, Xout, Cout);
}

extern "C" void kernel_launch(void* const* d_in, const int* in_sizes, int n_in,
                              void* d_out, int out_size) {
    const float* x  = (const float*)d_in[0];
    const float* w1 = (const float*)d_in[1];
    const float* g1 = (const float*)d_in[2];
    const float* b1 = (const float*)d_in[3];
    const float* w2 = (const float*)d_in[4];
    const float* g2 = (const float*)d_in[5];
    const float* b2 = (const float*)d_in[6];
    const float* w3 = (const float*)d_in[7];
    const float* g3 = (const float*)d_in[8];
    const float* b3 = (const float*)d_in[9];
    const float* w4 = (const float*)d_in[10];
    const float* g4 = (const float*)d_in[11];
    const float* b4 = (const float*)d_in[12];
    const float* w5 = (const float*)d_in[13];
    const float* g5 = (const float*)d_in[14];
    const float* b5 = (const float*)d_in[15];
    const float* we = (const float*)d_in[16];
    float* out = (float*)d_out;

    void *p_x1, *p_x2, *p_x3, *p_x4, *p_cat, *p_ac, *p_y, *p_wt;
    cudaGetSymbolAddress(&p_x1, g_x1);
    cudaGetSymbolAddress(&p_x2, g_x2);
    cudaGetSymbolAddress(&p_x3, g_x3);
    cudaGetSymbolAddress(&p_x4, g_x4);
    cudaGetSymbolAddress(&p_cat, g_cat);
    cudaGetSymbolAddress(&p_ac, g_ac);
    cudaGetSymbolAddress(&p_y, g_y);
    cudaGetSymbolAddress(&p_wt, g_wt);

    edge_layer(x,             3,  w1, g1, b1, 64,  (float*)p_x1, (float*)p_wt, (float*)p_ac);
    edge_layer((float*)p_x1,  64, w2, g2, b2, 64,  (float*)p_x2, (float*)p_wt, (float*)p_ac);
    edge_layer((float*)p_x2,  64, w3, g3, b3, 128, (float*)p_x3, (float*)p_wt, (float*)p_ac);
    edge_layer((float*)p_x3, 128, w4, g4, b4, 256, (float*)p_x4, (float*)p_wt, (float*)p_ac);

    k_cat<<<(BN * 512 + 255) / 256, 256>>>();
    k_gemm_nt<<<dim3(512 / 64, BN / 64), 256>>>((const float*)p_cat, w5, (float*)p_y,
                                                BN, 512, 512);
    k_zero_sums<<<1, 512>>>();
    k_pool5_partial<<<dim3(16, BB), 512>>>();
    k_pool5_fin<<<BB, 512>>>(g5, b5);
    k_embed<<<BB, 128>>>(we, out);
}

// round 3
// speedup vs baseline: 1.1981x; 1.1981x over previous
#include <cuda_runtime.h>
#include <float.h>
#include <cstdint>

#define BB   16
#define NPTS 2048
#define BN   (BB * NPTS)
#define KNN  20
#define EPSBN 1e-5f
#define SLOPE 0.2f

// ---------------- scratch (device globals; no allocation allowed) ----------------
__device__ float g_dist[(size_t)BB * NPTS * NPTS];   // 268 MB neg-distance matrix
__device__ float g_xx[BN];
__device__ int   g_idx[BN * KNN];
__device__ float g_x1[BN * 64];
__device__ float g_x2[BN * 64];
__device__ float g_x3[BN * 128];
__device__ float g_x4[BN * 256];
__device__ float g_cat[(size_t)BN * 512];
__device__ float g_ac[(size_t)BN * 512];    // [A | Cc] per edge layer
__device__ float g_y[(size_t)BN * 512];     // conv5 pre-BN
__device__ float g_mx[(size_t)BN * 256];
__device__ float g_mn[(size_t)BN * 256];
__device__ float g_wt[512 * 128];           // transformed weights [2Cout, Cin]
__device__ double g_sum[512];
__device__ double g_sq[512];
__device__ float g_p5max[BB * 16 * 512];
__device__ float g_p5min[BB * 16 * 512];
__device__ float g_z[BB * 512];

// ---------------- small kernels ----------------

__global__ void k_zero_sums() {
    g_sum[threadIdx.x] = 0.0;
    g_sq[threadIdx.x]  = 0.0;
}

__global__ void k_sqnorm(const float* __restrict__ X, int C) {
    int i = blockIdx.x * blockDim.x + threadIdx.x;
    if (i >= BN) return;
    const float* row = X + (size_t)i * C;
    float s = 0.f;
    for (int c = 0; c < C; c++) s += row[c] * row[c];
    g_xx[i] = s;
}

// ---------------- 128x128 tile SGEMM core (NT: C[m,n] = sum_k A[m,k]*B[n,k]) ----

// Loads a 128x16 tile of a row-major [rows, K] matrix into smem transposed
// S[kk][m]. Vector path requires K % 16 == 0 (true for K = 64,128,512).
__device__ __forceinline__ void load_tile_vec(const float* __restrict__ P, int ldk,
                                              int base_row, int k0,
                                              float (*S)[128], int tid) {
    int row = tid >> 2;              // 0..63
    int c4  = (tid & 3) * 4;         // 0,4,8,12
#pragma unroll
    for (int r = 0; r < 128; r += 64) {
        const float4 v = *reinterpret_cast<const float4*>(
            &P[(size_t)(base_row + row + r) * ldk + k0 + c4]);
        S[c4 + 0][row + r] = v.x;
        S[c4 + 1][row + r] = v.y;
        S[c4 + 2][row + r] = v.z;
        S[c4 + 3][row + r] = v.w;
    }
}

__device__ __forceinline__ void load_tile_scalar(const float* __restrict__ P, int ldk, int K,
                                                 int base_row, int k0,
                                                 float (*S)[128], int tid) {
#pragma unroll
    for (int e = 0; e < 8; e++) {
        int i = tid + e * 256;
        int m = i & 127, kk = i >> 7;
        int gk = k0 + kk;
        S[kk][m] = (gk < K) ? P[(size_t)(base_row + m) * ldk + gk] : 0.f;
    }
}

#define GEMM_CORE(EPILOGUE)                                                    \
    __shared__ float As[16][128];                                              \
    __shared__ float Bs[16][128];                                              \
    int tid = threadIdx.x;                                                     \
    int tx = tid & 15, ty = tid >> 4;                                          \
    float acc[8][8] = {};                                                      \
    bool vec = (K % 16) == 0;                                                  \
    for (int k0 = 0; k0 < K; k0 += 16) {                                       \
        if (vec) {                                                             \
            load_tile_vec(A, K, bm, k0, As, tid);                              \
            load_tile_vec(B, K, bn, k0, Bs, tid);                              \
        } else {                                                               \
            load_tile_scalar(A, K, K, bm, k0, As, tid);                        \
            load_tile_scalar(B, K, K, bn, k0, Bs, tid);                        \
        }                                                                      \
        __syncthreads();                                                       \
        _Pragma("unroll")                                                      \
        for (int kk = 0; kk < 16; kk++) {                                      \
            float a[8], bv[8];                                                 \
            *(float4*)&a[0]  = *(float4*)&As[kk][ty * 8];                      \
            *(float4*)&a[4]  = *(float4*)&As[kk][ty * 8 + 4];                  \
            *(float4*)&bv[0] = *(float4*)&Bs[kk][tx * 8];                      \
            *(float4*)&bv[4] = *(float4*)&Bs[kk][tx * 8 + 4];                  \
            _Pragma("unroll")                                                  \
            for (int u = 0; u < 8; u++)                                        \
                _Pragma("unroll")                                              \
                for (int v = 0; v < 8; v++) acc[u][v] += a[u] * bv[v];         \
        }                                                                      \
        __syncthreads();                                                       \
    }                                                                          \
    EPILOGUE

// Generic NT GEMM: grid (N/128, M/128), block 256
__global__ __launch_bounds__(256, 2)
void k_gemm128(const float* __restrict__ A, const float* __restrict__ B,
               float* __restrict__ Cm, int M, int N, int K) {
    int bm = blockIdx.y * 128, bn = blockIdx.x * 128;
    GEMM_CORE({
        for (int u = 0; u < 8; u++) {
            size_t ro = (size_t)(bm + ty * 8 + u) * N + bn + tx * 8;
            float4 o0 = make_float4(acc[u][0], acc[u][1], acc[u][2], acc[u][3]);
            float4 o1 = make_float4(acc[u][4], acc[u][5], acc[u][6], acc[u][7]);
            *reinterpret_cast<float4*>(&Cm[ro])     = o0;
            *reinterpret_cast<float4*>(&Cm[ro + 4]) = o1;
        }
    })
}

// Distance kernel: per batch b, D[i,j] = 2*<x_i,x_j> - xx_i - xx_j
__global__ __launch_bounds__(256, 2)
void k_dist128(const float* __restrict__ X, int K) {
    int b = blockIdx.z;
    const float* A = X + (size_t)b * NPTS * K;
    const float* B = A;
    const float* xxb = g_xx + b * NPTS;
    float* Db = g_dist + (size_t)b * NPTS * NPTS;
    int bm = blockIdx.y * 128, bn = blockIdx.x * 128;
    GEMM_CORE({
        float xj[8];
        *(float4*)&xj[0] = *(const float4*)&xxb[bn + tx * 8];
        *(float4*)&xj[4] = *(const float4*)&xxb[bn + tx * 8 + 4];
        for (int u = 0; u < 8; u++) {
            int i = bm + ty * 8 + u;
            float xi = xxb[i];
            size_t ro = (size_t)i * NPTS + bn + tx * 8;
            float4 o0 = make_float4(2.f * acc[u][0] - xi - xj[0],
                                    2.f * acc[u][1] - xi - xj[1],
                                    2.f * acc[u][2] - xi - xj[2],
                                    2.f * acc[u][3] - xi - xj[3]);
            float4 o1 = make_float4(2.f * acc[u][4] - xi - xj[4],
                                    2.f * acc[u][5] - xi - xj[5],
                                    2.f * acc[u][6] - xi - xj[6],
                                    2.f * acc[u][7] - xi - xj[7]);
            *reinterpret_cast<float4*>(&Db[ro])     = o0;
            *reinterpret_cast<float4*>(&Db[ro + 4]) = o1;
        }
    })
}

// warp per row: top-20 (set semantics only; order irrelevant downstream)
__global__ void k_topk() {
    int gw   = (blockIdx.x * blockDim.x + threadIdx.x) >> 5;
    int lane = threadIdx.x & 31;
    if (gw >= BN) return;
    const float* row = g_dist + (size_t)gw * NPTS;

    float v[KNN]; int id[KNN];
#pragma unroll
    for (int t = 0; t < KNN; t++) { v[t] = -FLT_MAX; id[t] = -1; }

    for (int j = lane; j < NPTS; j += 32) {
        float d = row[j];
        if (d > v[KNN - 1]) {
            int pos = KNN - 1;
            while (pos > 0 && v[pos - 1] < d) {
                v[pos] = v[pos - 1]; id[pos] = id[pos - 1]; pos--;
            }
            v[pos] = d; id[pos] = j;
        }
    }
    int p = 0;
    for (int t = 0; t < KNN; t++) {
        float bh = (p < KNN) ? v[p] : -FLT_MAX;
        int   bl = lane;
        for (int off = 16; off > 0; off >>= 1) {
            float oh = __shfl_down_sync(0xffffffffu, bh, off);
            int   ol = __shfl_down_sync(0xffffffffu, bl, off);
            if (oh > bh) { bh = oh; bl = ol; }
        }
        bl = __shfl_sync(0xffffffffu, bl, 0);
        int hid  = (p < KNN) ? id[p] : -1;
        int widx = __shfl_sync(0xffffffffu, hid, bl);
        if (lane == 0) g_idx[gw * KNN + t] = widx;
        if (lane == bl) p++;
    }
}

// wt[co] = W_d ; wt[Cout+co] = W_c - W_d
__global__ void k_transform_w(const float* __restrict__ w, float* __restrict__ wt,
                              int Cout, int Cin) {
    int i = blockIdx.x * blockDim.x + threadIdx.x;
    if (i >= Cout * Cin) return;
    int co = i / Cin, ci = i % Cin;
    float wd = w[co * 2 * Cin + ci];
    float wc = w[co * 2 * Cin + Cin + ci];
    wt[co * Cin + ci] = wd;
    wt[(Cout + co) * Cin + ci] = wc - wd;
}

// per point: gather neighbors' A rows, y = A[idx]+Cc; track max/min over k + channel stats
__global__ void k_edge_pool(const float* __restrict__ AC, int Cout) {
    int bn = blockIdx.x;                 // b*NPTS + n
    __shared__ int sidx[KNN];
    if (threadIdx.x < KNN) sidx[threadIdx.x] = g_idx[bn * KNN + threadIdx.x];
    __syncthreads();
    int b = bn / NPTS;
    const float* ACb = AC + (size_t)b * NPTS * 2 * Cout;
    int co = threadIdx.x;                // blockDim == Cout
    float cc = AC[(size_t)bn * 2 * Cout + Cout + co];
    float vmax = -FLT_MAX, vmin = FLT_MAX, s = 0.f, s2 = 0.f;
#pragma unroll
    for (int kk = 0; kk < KNN; kk++) {
        float y = ACb[(size_t)sidx[kk] * 2 * Cout + co] + cc;
        vmax = fmaxf(vmax, y); vmin = fminf(vmin, y);
        s += y; s2 += y * y;
    }
    g_mx[(size_t)bn * Cout + co] = vmax;
    g_mn[(size_t)bn * Cout + co] = vmin;
    atomicAdd(&g_sum[co], (double)s);
    atomicAdd(&g_sq[co], (double)s2);
}

__global__ void k_edge_fin(const float* __restrict__ gamma, const float* __restrict__ beta,
                           float* __restrict__ Xout, int Cout) {
    int i = blockIdx.x * blockDim.x + threadIdx.x;
    if (i >= BN * Cout) return;
    int co = i % Cout;
    double cnt  = (double)BN * (double)KNN;
    double mean = g_sum[co] / cnt;
    double var  = g_sq[co] / cnt - mean * mean;
    float sc    = gamma[co] * rsqrtf((float)var + EPSBN);
    float m     = (sc >= 0.f) ? g_mx[i] : g_mn[i];
    float v     = (m - (float)mean) * sc + beta[co];
    Xout[i] = (v > 0.f) ? v : SLOPE * v;
}

__global__ void k_cat() {
    int i = blockIdx.x * blockDim.x + threadIdx.x;
    if (i >= BN * 512) return;
    int n = i >> 9, c = i & 511;
    float v;
    if      (c < 64)  v = g_x1[n * 64 + c];
    else if (c < 128) v = g_x2[n * 64 + (c - 64)];
    else if (c < 256) v = g_x3[(size_t)n * 128 + (c - 128)];
    else              v = g_x4[(size_t)n * 256 + (c - 256)];
    g_cat[i] = v;
}

__global__ void k_pool5_partial() {
    int b = blockIdx.y, chunk = blockIdx.x;   // 16 chunks of 128 rows
    int c = threadIdx.x;                      // 512 threads
    float mx = -FLT_MAX, mn = FLT_MAX, s = 0.f, s2 = 0.f;
    int r0 = chunk * 128;
    for (int r = r0; r < r0 + 128; r++) {
        float v = g_y[((size_t)b * NPTS + r) * 512 + c];
        mx = fmaxf(mx, v); mn = fminf(mn, v);
        s += v; s2 += v * v;
    }
    g_p5max[(b * 16 + chunk) * 512 + c] = mx;
    g_p5min[(b * 16 + chunk) * 512 + c] = mn;
    atomicAdd(&g_sum[c], (double)s);
    atomicAdd(&g_sq[c], (double)s2);
}

__global__ void k_pool5_fin(const float* __restrict__ gamma, const float* __restrict__ beta) {
    int b = blockIdx.x, c = threadIdx.x;
    double cnt  = (double)BN;
    double mean = g_sum[c] / cnt;
    double var  = g_sq[c] / cnt - mean * mean;
    float sc    = gamma[c] * rsqrtf((float)var + EPSBN);
    float mx = -FLT_MAX, mn = FLT_MAX;
    for (int t = 0; t < 16; t++) {
        mx = fmaxf(mx, g_p5max[(b * 16 + t) * 512 + c]);
        mn = fminf(mn, g_p5min[(b * 16 + t) * 512 + c]);
    }
    float m = (sc >= 0.f) ? mx : mn;
    float v = (m - (float)mean) * sc + beta[c];
    g_z[b * 512 + c] = (v > 0.f) ? v : SLOPE * v;
}

__global__ void k_embed(const float* __restrict__ we, float* __restrict__ out) {
    int b = blockIdx.x, f = threadIdx.x;      // 128 threads
    const float* z  = g_z + b * 512;
    const float* wr = we + f * 512;
    float s = 0.f;
    for (int c = 0; c < 512; c++) s += z[c] * wr[c];
    out[b * 128 + f] = s;
}

// ---------------- host ----------------

static void edge_layer(const float* Xin, int Cin,
                       const float* w, const float* gamma, const float* beta,
                       int Cout, float* Xout, float* p_wt, float* p_ac) {
    // kNN on Xin
    k_sqnorm<<<BN / 256, 256>>>(Xin, Cin);
    dim3 dg(NPTS / 128, NPTS / 128, BB);
    k_dist128<<<dg, 256>>>(Xin, Cin);
    k_topk<<<BN / 4, 128>>>();
    // transformed-weight GEMM: [A | Cc]
    int tw = Cout * Cin;
    k_transform_w<<<(tw + 255) / 256, 256>>>(w, p_wt, Cout, Cin);
    k_gemm128<<<dim3(2 * Cout / 128, BN / 128), 256>>>(Xin, p_wt, p_ac, BN, 2 * Cout, Cin);
    // pool + BN stats + finalize
    k_zero_sums<<<1, 512>>>();
    k_edge_pool<<<BN, Cout>>>(p_ac, Cout);
    k_edge_fin<<<(BN * Cout + 255) / 256, 256>>>(gamma, beta, Xout, Cout);
}

extern "C" void kernel_launch(void* const* d_in, const int* in_sizes, int n_in,
                              void* d_out, int out_size) {
    const float* x  = (const float*)d_in[0];
    const float* w1 = (const float*)d_in[1];
    const float* g1 = (const float*)d_in[2];
    const float* b1 = (const float*)d_in[3];
    const float* w2 = (const float*)d_in[4];
    const float* g2 = (const float*)d_in[5];
    const float* b2 = (const float*)d_in[6];
    const float* w3 = (const float*)d_in[7];
    const float* g3 = (const float*)d_in[8];
    const float* b3 = (const float*)d_in[9];
    const float* w4 = (const float*)d_in[10];
    const float* g4 = (const float*)d_in[11];
    const float* b4 = (const float*)d_in[12];
    const float* w5 = (const float*)d_in[13];
    const float* g5 = (const float*)d_in[14];
    const float* b5 = (const float*)d_in[15];
    const float* we = (const float*)d_in[16];
    float* out = (float*)d_out;

    void *p_x1, *p_x2, *p_x3, *p_x4, *p_cat, *p_ac, *p_y, *p_wt;
    cudaGetSymbolAddress(&p_x1, g_x1);
    cudaGetSymbolAddress(&p_x2, g_x2);
    cudaGetSymbolAddress(&p_x3, g_x3);
    cudaGetSymbolAddress(&p_x4, g_x4);
    cudaGetSymbolAddress(&p_cat, g_cat);
    cudaGetSymbolAddress(&p_ac, g_ac);
    cudaGetSymbolAddress(&p_y, g_y);
    cudaGetSymbolAddress(&p_wt, g_wt);

    edge_layer(x,             3,  w1, g1, b1, 64,  (float*)p_x1, (float*)p_wt, (float*)p_ac);
    edge_layer((float*)p_x1,  64, w2, g2, b2, 64,  (float*)p_x2, (float*)p_wt, (float*)p_ac);
    edge_layer((float*)p_x2,  64, w3, g3, b3, 128, (float*)p_x3, (float*)p_wt, (float*)p_ac);
    edge_layer((float*)p_x3, 128, w4, g4, b4, 256, (float*)p_x4, (float*)p_wt, (float*)p_ac);

    k_cat<<<(BN * 512 + 255) / 256, 256>>>();
    k_gemm128<<<dim3(512 / 128, BN / 128), 256>>>((const float*)p_cat, w5, (float*)p_y,
                                                  BN, 512, 512);
    k_zero_sums<<<1, 512>>>();
    k_pool5_partial<<<dim3(16, BB), 512>>>();
    k_pool5_fin<<<BB, 512>>>(g5, b5);
    k_embed<<<BB, 128>>>(we, out);
}

// round 4
// speedup vs baseline: 1.4049x; 1.1726x over previous
#include <cuda_runtime.h>
#include <float.h>
#include <cstdint>

#define BB   16
#define NPTS 2048
#define BN   (BB * NPTS)
#define KNN  20
#define PPB  32            // points per edge_pool block
#define EPSBN 1e-5f
#define SLOPE 0.2f

// ---------------- scratch (device globals) ----------------
__device__ float g_dist[(size_t)BB * NPTS * NPTS];   // 268 MB neg-distance matrix
__device__ float g_xx[BN];
__device__ int   g_idx[BN * KNN];
__device__ float g_cat[(size_t)BN * 512];   // x1|x2|x3|x4 slices, row stride 512
__device__ float g_ac[(size_t)BN * 512];    // [A | Cc] per edge layer
__device__ float g_y[(size_t)BN * 512];     // conv5 pre-BN
__device__ float g_mx[(size_t)BN * 256];
__device__ float g_mn[(size_t)BN * 256];
__device__ float g_wt[512 * 128];           // transformed weights [2Cout, Cin]
__device__ double g_sum[512];
__device__ double g_sq[512];
__device__ float g_p5max[BB * 16 * 512];
__device__ float g_p5min[BB * 16 * 512];
__device__ float g_z[BB * 512];

// ---------------- small kernels ----------------

__global__ void k_zero_sums() {
    g_sum[threadIdx.x] = 0.0;
    g_sq[threadIdx.x]  = 0.0;
}

__global__ void k_sqnorm(const float* __restrict__ X, int ld, int C) {
    int i = blockIdx.x * blockDim.x + threadIdx.x;
    if (i >= BN) return;
    const float* row = X + (size_t)i * ld;
    float s = 0.f;
    for (int c = 0; c < C; c++) s += row[c] * row[c];
    g_xx[i] = s;
}

// ---------- 128x128 tile SGEMM core, double-buffered (NT: C=A·B^T) ----------

__device__ __forceinline__ void load_tile_scalar(const float* __restrict__ P, int ld, int K,
                                                 int base_row, int k0,
                                                 float (*S)[128], int tid) {
#pragma unroll
    for (int e = 0; e < 8; e++) {
        int i = tid + e * 256;
        int m = i & 127, kk = i >> 7;
        int gk = k0 + kk;
        S[kk][m] = (gk < K) ? P[(size_t)(base_row + m) * ld + gk] : 0.f;
    }
}

#define ST_TILE(S, r0, r1)                                                     \
    do {                                                                       \
        S[c4 + 0][row] = r0.x; S[c4 + 1][row] = r0.y;                          \
        S[c4 + 2][row] = r0.z; S[c4 + 3][row] = r0.w;                          \
        S[c4 + 0][row + 64] = r1.x; S[c4 + 1][row + 64] = r1.y;                \
        S[c4 + 2][row + 64] = r1.z; S[c4 + 3][row + 64] = r1.w;                \
    } while (0)

#define COMPUTE_SLAB(AS, BS)                                                   \
    _Pragma("unroll")                                                          \
    for (int kk = 0; kk < 16; kk++) {                                          \
        float a[8], bv[8];                                                     \
        *(float4*)&a[0]  = *(const float4*)&AS[kk][ty * 8];                    \
        *(float4*)&a[4]  = *(const float4*)&AS[kk][ty * 8 + 4];                \
        *(float4*)&bv[0] = *(const float4*)&BS[kk][tx * 8];                    \
        *(float4*)&bv[4] = *(const float4*)&BS[kk][tx * 8 + 4];                \
        _Pragma("unroll")                                                      \
        for (int u = 0; u < 8; u++)                                            \
            _Pragma("unroll")                                                  \
            for (int v = 0; v < 8; v++) acc[u][v] += a[u] * bv[v];             \
    }

#define GEMM_CORE(EPILOGUE)                                                    \
    __shared__ float As[2][16][128];                                           \
    __shared__ float Bs[2][16][128];                                           \
    int tid = threadIdx.x;                                                     \
    int tx = tid & 15, ty = tid >> 4;                                          \
    float acc[8][8] = {};                                                      \
    if ((K & 15) == 0) {                                                       \
        int row = tid >> 2, c4 = (tid & 3) * 4;                                \
        const float* pa0 = A + (size_t)(bm + row) * lda + c4;                  \
        const float* pa1 = A + (size_t)(bm + row + 64) * lda + c4;             \
        const float* pb0 = B + (size_t)(bn + row) * ldb + c4;                  \
        const float* pb1 = B + (size_t)(bn + row + 64) * ldb + c4;             \
        float4 ra0 = *(const float4*)pa0;                                      \
        float4 ra1 = *(const float4*)pa1;                                      \
        float4 rb0 = *(const float4*)pb0;                                      \
        float4 rb1 = *(const float4*)pb1;                                      \
        ST_TILE(As[0], ra0, ra1);                                              \
        ST_TILE(Bs[0], rb0, rb1);                                              \
        __syncthreads();                                                       \
        int buf = 0;                                                           \
        for (int k0 = 0; k0 < K; k0 += 16) {                                   \
            bool nxt = (k0 + 16) < K;                                          \
            if (nxt) {                                                         \
                ra0 = *(const float4*)(pa0 + k0 + 16);                         \
                ra1 = *(const float4*)(pa1 + k0 + 16);                         \
                rb0 = *(const float4*)(pb0 + k0 + 16);                         \
                rb1 = *(const float4*)(pb1 + k0 + 16);                         \
            }                                                                  \
            if (buf == 0) { COMPUTE_SLAB(As[0], Bs[0]); }                      \
            else          { COMPUTE_SLAB(As[1], Bs[1]); }                      \
            if (nxt) {                                                         \
                if (buf == 0) { ST_TILE(As[1], ra0, ra1); ST_TILE(Bs[1], rb0, rb1); } \
                else          { ST_TILE(As[0], ra0, ra1); ST_TILE(Bs[0], rb0, rb1); } \
                __syncthreads();                                               \
                buf ^= 1;                                                      \
            }                                                                  \
        }                                                                      \
    } else {                                                                   \
        for (int k0 = 0; k0 < K; k0 += 16) {                                   \
            load_tile_scalar(A, lda, K, bm, k0, As[0], tid);                   \
            load_tile_scalar(B, ldb, K, bn, k0, Bs[0], tid);                   \
            __syncthreads();                                                   \
            COMPUTE_SLAB(As[0], Bs[0]);                                        \
            __syncthreads();                                                   \
        }                                                                      \
    }                                                                          \
    EPILOGUE

// Generic NT GEMM: grid (N/128, M/128), block 256
__global__ __launch_bounds__(256, 2)
void k_gemm128(const float* __restrict__ A, int lda,
               const float* __restrict__ B, int ldb,
               float* __restrict__ Cm, int ldc, int K) {
    int bm = blockIdx.y * 128, bn = blockIdx.x * 128;
    GEMM_CORE({
        for (int u = 0; u < 8; u++) {
            size_t ro = (size_t)(bm + ty * 8 + u) * ldc + bn + tx * 8;
            float4 o0 = make_float4(acc[u][0], acc[u][1], acc[u][2], acc[u][3]);
            float4 o1 = make_float4(acc[u][4], acc[u][5], acc[u][6], acc[u][7]);
            *reinterpret_cast<float4*>(&Cm[ro])     = o0;
            *reinterpret_cast<float4*>(&Cm[ro + 4]) = o1;
        }
    })
}

// Distance kernel: per batch b, D[i,j] = 2*<x_i,x_j> - xx_i - xx_j
__global__ __launch_bounds__(256, 2)
void k_dist128(const float* __restrict__ X, int ld, int K) {
    int b = blockIdx.z;
    const float* A = X + (size_t)b * NPTS * ld;
    const float* B = A;
    int lda = ld, ldb = ld;
    const float* xxb = g_xx + b * NPTS;
    float* Db = g_dist + (size_t)b * NPTS * NPTS;
    int bm = blockIdx.y * 128, bn = blockIdx.x * 128;
    GEMM_CORE({
        float xj[8];
        *(float4*)&xj[0] = *(const float4*)&xxb[bn + tx * 8];
        *(float4*)&xj[4] = *(const float4*)&xxb[bn + tx * 8 + 4];
        for (int u = 0; u < 8; u++) {
            int i = bm + ty * 8 + u;
            float xi = xxb[i];
            size_t ro = (size_t)i * NPTS + bn + tx * 8;
            float4 o0 = make_float4(2.f * acc[u][0] - xi - xj[0],
                                    2.f * acc[u][1] - xi - xj[1],
                                    2.f * acc[u][2] - xi - xj[2],
                                    2.f * acc[u][3] - xi - xj[3]);
            float4 o1 = make_float4(2.f * acc[u][4] - xi - xj[4],
                                    2.f * acc[u][5] - xi - xj[5],
                                    2.f * acc[u][6] - xi - xj[6],
                                    2.f * acc[u][7] - xi - xj[7]);
            *reinterpret_cast<float4*>(&Db[ro])     = o0;
            *reinterpret_cast<float4*>(&Db[ro + 4]) = o1;
        }
    })
}

// warp per row: top-20 (set semantics only)
__global__ void k_topk() {
    int gw   = (blockIdx.x * blockDim.x + threadIdx.x) >> 5;
    int lane = threadIdx.x & 31;
    if (gw >= BN) return;
    const float* row = g_dist + (size_t)gw * NPTS;

    float v[KNN]; int id[KNN];
#pragma unroll
    for (int t = 0; t < KNN; t++) { v[t] = -FLT_MAX; id[t] = -1; }

    for (int j = lane; j < NPTS; j += 32) {
        float d = row[j];
        if (d > v[KNN - 1]) {
            int pos = KNN - 1;
            while (pos > 0 && v[pos - 1] < d) {
                v[pos] = v[pos - 1]; id[pos] = id[pos - 1]; pos--;
            }
            v[pos] = d; id[pos] = j;
        }
    }
    int p = 0;
    for (int t = 0; t < KNN; t++) {
        float bh = (p < KNN) ? v[p] : -FLT_MAX;
        int   bl = lane;
        for (int off = 16; off > 0; off >>= 1) {
            float oh = __shfl_down_sync(0xffffffffu, bh, off);
            int   ol = __shfl_down_sync(0xffffffffu, bl, off);
            if (oh > bh) { bh = oh; bl = ol; }
        }
        bl = __shfl_sync(0xffffffffu, bl, 0);
        int hid  = (p < KNN) ? id[p] : -1;
        int widx = __shfl_sync(0xffffffffu, hid, bl);
        if (lane == 0) g_idx[gw * KNN + t] = widx;
        if (lane == bl) p++;
    }
}

// wt[co] = W_d ; wt[Cout+co] = W_c - W_d
__global__ void k_transform_w(const float* __restrict__ w, float* __restrict__ wt,
                              int Cout, int Cin) {
    int i = blockIdx.x * blockDim.x + threadIdx.x;
    if (i >= Cout * Cin) return;
    int co = i / Cin, ci = i % Cin;
    float wd = w[co * 2 * Cin + ci];
    float wc = w[co * 2 * Cin + Cin + ci];
    wt[co * Cin + ci] = wd;
    wt[(Cout + co) * Cin + ci] = wc - wd;
}

// PPB points per block; thread co loops points; one atomic per thread per array
__global__ void k_edge_pool(const float* __restrict__ AC, int Cout) {
    int p0 = blockIdx.x * PPB;           // first global point index
    int b  = p0 / NPTS;                  // PPB divides NPTS -> single batch
    const float* ACb = AC + (size_t)b * NPTS * 2 * Cout;
    __shared__ int sidx[PPB * KNN];
    for (int i = threadIdx.x; i < PPB * KNN; i += blockDim.x)
        sidx[i] = g_idx[p0 * KNN + i];
    __syncthreads();
    int co = threadIdx.x;                // blockDim == Cout
    float s = 0.f, s2 = 0.f;
    for (int p = 0; p < PPB; p++) {
        int bn = p0 + p;
        float cc = AC[(size_t)bn * 2 * Cout + Cout + co];
        float vmax = -FLT_MAX, vmin = FLT_MAX;
#pragma unroll
        for (int kk = 0; kk < KNN; kk++) {
            float y = ACb[(size_t)sidx[p * KNN + kk] * 2 * Cout + co] + cc;
            vmax = fmaxf(vmax, y); vmin = fminf(vmin, y);
            s += y; s2 += y * y;
        }
        g_mx[(size_t)bn * Cout + co] = vmax;
        g_mn[(size_t)bn * Cout + co] = vmin;
    }
    atomicAdd(&g_sum[co], (double)s);
    atomicAdd(&g_sq[co], (double)s2);
}

// finalize into g_cat slice (row stride ldo)
__global__ void k_edge_fin(const float* __restrict__ gamma, const float* __restrict__ beta,
                           float* __restrict__ Xout, int ldo, int Cout) {
    int i = blockIdx.x * blockDim.x + threadIdx.x;
    if (i >= BN * Cout) return;
    int co = i % Cout, n = i / Cout;
    double cnt  = (double)BN * (double)KNN;
    double mean = g_sum[co] / cnt;
    double var  = g_sq[co] / cnt - mean * mean;
    float sc    = gamma[co] * rsqrtf((float)var + EPSBN);
    float m     = (sc >= 0.f) ? g_mx[i] : g_mn[i];
    float v     = (m - (float)mean) * sc + beta[co];
    Xout[(size_t)n * ldo + co] = (v > 0.f) ? v : SLOPE * v;
}

__global__ void k_pool5_partial() {
    int b = blockIdx.y, chunk = blockIdx.x;   // 16 chunks of 128 rows
    int c = threadIdx.x;                      // 512 threads
    float mx = -FLT_MAX, mn = FLT_MAX, s = 0.f, s2 = 0.f;
    int r0 = chunk * 128;
    for (int r = r0; r < r0 + 128; r++) {
        float v = g_y[((size_t)b * NPTS + r) * 512 + c];
        mx = fmaxf(mx, v); mn = fminf(mn, v);
        s += v; s2 += v * v;
    }
    g_p5max[(b * 16 + chunk) * 512 + c] = mx;
    g_p5min[(b * 16 + chunk) * 512 + c] = mn;
    atomicAdd(&g_sum[c], (double)s);
    atomicAdd(&g_sq[c], (double)s2);
}

__global__ void k_pool5_fin(const float* __restrict__ gamma, const float* __restrict__ beta) {
    int b = blockIdx.x, c = threadIdx.x;
    double cnt  = (double)BN;
    double mean = g_sum[c] / cnt;
    double var  = g_sq[c] / cnt - mean * mean;
    float sc    = gamma[c] * rsqrtf((float)var + EPSBN);
    float mx = -FLT_MAX, mn = FLT_MAX;
    for (int t = 0; t < 16; t++) {
        mx = fmaxf(mx, g_p5max[(b * 16 + t) * 512 + c]);
        mn = fminf(mn, g_p5min[(b * 16 + t) * 512 + c]);
    }
    float m = (sc >= 0.f) ? mx : mn;
    float v = (m - (float)mean) * sc + beta[c];
    g_z[b * 512 + c] = (v > 0.f) ? v : SLOPE * v;
}

__global__ void k_embed(const float* __restrict__ we, float* __restrict__ out) {
    int b = blockIdx.x, f = threadIdx.x;      // 128 threads
    const float* z  = g_z + b * 512;
    const float* wr = we + f * 512;
    float s = 0.f;
    for (int c = 0; c < 512; c++) s += z[c] * wr[c];
    out[b * 128 + f] = s;
}

// ---------------- host ----------------

static void edge_layer(const float* Xin, int ldx, int Cin,
                       const float* w, const float* gamma, const float* beta,
                       int Cout, float* Xout, int ldo, float* p_wt, float* p_ac) {
    k_sqnorm<<<BN / 256, 256>>>(Xin, ldx, Cin);
    dim3 dg(NPTS / 128, NPTS / 128, BB);
    k_dist128<<<dg, 256>>>(Xin, ldx, Cin);
    k_topk<<<BN / 4, 128>>>();
    int tw = Cout * Cin;
    k_transform_w<<<(tw + 255) / 256, 256>>>(w, p_wt, Cout, Cin);
    k_gemm128<<<dim3(2 * Cout / 128, BN / 128), 256>>>(Xin, ldx, p_wt, Cin,
                                                       p_ac, 2 * Cout, Cin);
    k_zero_sums<<<1, 512>>>();
    k_edge_pool<<<BN / PPB, Cout>>>(p_ac, Cout);
    k_edge_fin<<<(BN * Cout + 255) / 256, 256>>>(gamma, beta, Xout, ldo, Cout);
}

extern "C" void kernel_launch(void* const* d_in, const int* in_sizes, int n_in,
                              void* d_out, int out_size) {
    const float* x  = (const float*)d_in[0];
    const float* w1 = (const float*)d_in[1];
    const float* g1 = (const float*)d_in[2];
    const float* b1 = (const float*)d_in[3];
    const float* w2 = (const float*)d_in[4];
    const float* g2 = (const float*)d_in[5];
    const float* b2 = (const float*)d_in[6];
    const float* w3 = (const float*)d_in[7];
    const float* g3 = (const float*)d_in[8];
    const float* b3 = (const float*)d_in[9];
    const float* w4 = (const float*)d_in[10];
    const float* g4 = (const float*)d_in[11];
    const float* b4 = (const float*)d_in[12];
    const float* w5 = (const float*)d_in[13];
    const float* g5 = (const float*)d_in[14];
    const float* b5 = (const float*)d_in[15];
    const float* we = (const float*)d_in[16];
    float* out = (float*)d_out;

    void *p_cat, *p_ac, *p_y, *p_wt;
    cudaGetSymbolAddress(&p_cat, g_cat);
    cudaGetSymbolAddress(&p_ac, g_ac);
    cudaGetSymbolAddress(&p_y, g_y);
    cudaGetSymbolAddress(&p_wt, g_wt);
    float* cat = (float*)p_cat;
    float* wt  = (float*)p_wt;
    float* ac  = (float*)p_ac;

    // x1 -> cat[:,0:64], x2 -> cat[:,64:128], x3 -> cat[:,128:256], x4 -> cat[:,256:512]
    edge_layer(x,         3,   3,   w1, g1, b1, 64,  cat + 0,   512, wt, ac);
    edge_layer(cat + 0,   512, 64,  w2, g2, b2, 64,  cat + 64,  512, wt, ac);
    edge_layer(cat + 64,  512, 64,  w3, g3, b3, 128, cat + 128, 512, wt, ac);
    edge_layer(cat + 128, 512, 128, w4, g4, b4, 256, cat + 256, 512, wt, ac);

    k_gemm128<<<dim3(512 / 128, BN / 128), 256>>>(cat, 512, w5, 512,
                                                  (float*)p_y, 512, 512);
    k_zero_sums<<<1, 512>>>();
    k_pool5_partial<<<dim3(16, BB), 512>>>();
    k_pool5_fin<<<BB, 512>>>(g5, b5);
    k_embed<<<BB, 128>>>(we, out);
}

// round 5
// speedup vs baseline: 1.4706x; 1.0468x over previous
#include <cuda_runtime.h>
#include <float.h>
#include <cstdint>

#define BB   16
#define NPTS 2048
#define BN   (BB * NPTS)
#define KNN  20
#define PPB  32            // points per edge_pool block
#define EPSBN 1e-5f
#define SLOPE 0.2f
#define NTILE (NPTS / 128)            // 16 row-tiles
#define NPAIR (NTILE * (NTILE + 1) / 2)   // 136 triangular block pairs

// ---------------- scratch (device globals) ----------------
__device__ float g_dist[(size_t)BB * NPTS * NPTS];   // 268 MB neg-distance matrix
__device__ float g_xx[BN];
__device__ int   g_idx[BN * KNN];
__device__ float g_cat[(size_t)BN * 512];   // x1|x2|x3|x4 slices, row stride 512
__device__ float g_ac[(size_t)BN * 512];    // [A | Cc] per edge layer
__device__ float g_y[(size_t)BN * 512];     // conv5 pre-BN
__device__ float g_mx[(size_t)BN * 256];
__device__ float g_mn[(size_t)BN * 256];
__device__ float g_wt[4][512 * 128];        // transformed weights per layer [2Cout, Cin]
__device__ double g_sum[512];
__device__ double g_sq[512];
__device__ float g_p5max[BB * 16 * 512];
__device__ float g_p5min[BB * 16 * 512];
__device__ float g_z[BB * 512];

// ---------------- small kernels ----------------

__global__ void k_zero_sums() {
    g_sum[threadIdx.x] = 0.0;
    g_sq[threadIdx.x]  = 0.0;
}

__global__ void k_sqnorm(const float* __restrict__ X, int ld, int C) {
    int i = blockIdx.x * blockDim.x + threadIdx.x;
    if (i >= BN) return;
    const float* row = X + (size_t)i * ld;
    float s = 0.f;
    for (int c = 0; c < C; c++) s += row[c] * row[c];
    g_xx[i] = s;
}

// ---------- 128x128 tile SGEMM core, double-buffered (NT: C=A·B^T) ----------

__device__ __forceinline__ void load_tile_scalar(const float* __restrict__ P, int ld, int K,
                                                 int base_row, int k0,
                                                 float (*S)[128], int tid) {
#pragma unroll
    for (int e = 0; e < 8; e++) {
        int i = tid + e * 256;
        int m = i & 127, kk = i >> 7;
        int gk = k0 + kk;
        S[kk][m] = (gk < K) ? P[(size_t)(base_row + m) * ld + gk] : 0.f;
    }
}

#define ST_TILE(S, r0, r1)                                                     \
    do {                                                                       \
        S[c4 + 0][row] = r0.x; S[c4 + 1][row] = r0.y;                          \
        S[c4 + 2][row] = r0.z; S[c4 + 3][row] = r0.w;                          \
        S[c4 + 0][row + 64] = r1.x; S[c4 + 1][row + 64] = r1.y;                \
        S[c4 + 2][row + 64] = r1.z; S[c4 + 3][row + 64] = r1.w;                \
    } while (0)

#define COMPUTE_SLAB(AS, BS)                                                   \
    _Pragma("unroll")                                                          \
    for (int kk = 0; kk < 16; kk++) {                                          \
        float a[8], bv[8];                                                     \
        *(float4*)&a[0]  = *(const float4*)&AS[kk][ty * 8];                    \
        *(float4*)&a[4]  = *(const float4*)&AS[kk][ty * 8 + 4];                \
        *(float4*)&bv[0] = *(const float4*)&BS[kk][tx * 8];                    \
        *(float4*)&bv[4] = *(const float4*)&BS[kk][tx * 8 + 4];                \
        _Pragma("unroll")                                                      \
        for (int u = 0; u < 8; u++)                                            \
            _Pragma("unroll")                                                  \
            for (int v = 0; v < 8; v++) acc[u][v] += a[u] * bv[v];             \
    }

#define GEMM_CORE(EPILOGUE)                                                    \
    __shared__ float As[2][16][128];                                           \
    __shared__ float Bs[2][16][128];                                           \
    int tid = threadIdx.x;                                                     \
    int tx = tid & 15, ty = tid >> 4;                                          \
    float acc[8][8] = {};                                                      \
    if ((K & 15) == 0) {                                                       \
        int row = tid >> 2, c4 = (tid & 3) * 4;                                \
        const float* pa0 = A + (size_t)(bm + row) * lda + c4;                  \
        const float* pa1 = A + (size_t)(bm + row + 64) * lda + c4;             \
        const float* pb0 = B + (size_t)(bn + row) * ldb + c4;                  \
        const float* pb1 = B + (size_t)(bn + row + 64) * ldb + c4;             \
        float4 ra0 = *(const float4*)pa0;                                      \
        float4 ra1 = *(const float4*)pa1;                                      \
        float4 rb0 = *(const float4*)pb0;                                      \
        float4 rb1 = *(const float4*)pb1;                                      \
        ST_TILE(As[0], ra0, ra1);                                              \
        ST_TILE(Bs[0], rb0, rb1);                                              \
        __syncthreads();                                                       \
        int buf = 0;                                                           \
        for (int k0 = 0; k0 < K; k0 += 16) {                                   \
            bool nxt = (k0 + 16) < K;                                          \
            if (nxt) {                                                         \
                ra0 = *(const float4*)(pa0 + k0 + 16);                         \
                ra1 = *(const float4*)(pa1 + k0 + 16);                         \
                rb0 = *(const float4*)(pb0 + k0 + 16);                         \
                rb1 = *(const float4*)(pb1 + k0 + 16);                         \
            }                                                                  \
            if (buf == 0) { COMPUTE_SLAB(As[0], Bs[0]); }                      \
            else          { COMPUTE_SLAB(As[1], Bs[1]); }                      \
            if (nxt) {                                                         \
                if (buf == 0) { ST_TILE(As[1], ra0, ra1); ST_TILE(Bs[1], rb0, rb1); } \
                else          { ST_TILE(As[0], ra0, ra1); ST_TILE(Bs[0], rb0, rb1); } \
                __syncthreads();                                               \
                buf ^= 1;                                                      \
            }                                                                  \
        }                                                                      \
    } else {                                                                   \
        for (int k0 = 0; k0 < K; k0 += 16) {                                   \
            load_tile_scalar(A, lda, K, bm, k0, As[0], tid);                   \
            load_tile_scalar(B, ldb, K, bn, k0, Bs[0], tid);                   \
            __syncthreads();                                                   \
            COMPUTE_SLAB(As[0], Bs[0]);                                        \
            __syncthreads();                                                   \
        }                                                                      \
    }                                                                          \
    EPILOGUE

// Generic NT GEMM: grid (N/128, M/128), block 256
__global__ __launch_bounds__(256, 2)
void k_gemm128(const float* __restrict__ A, int lda,
               const float* __restrict__ B, int ldb,
               float* __restrict__ Cm, int ldc, int K) {
    int bm = blockIdx.y * 128, bn = blockIdx.x * 128;
    GEMM_CORE({
        for (int u = 0; u < 8; u++) {
            size_t ro = (size_t)(bm + ty * 8 + u) * ldc + bn + tx * 8;
            float4 o0 = make_float4(acc[u][0], acc[u][1], acc[u][2], acc[u][3]);
            float4 o1 = make_float4(acc[u][4], acc[u][5], acc[u][6], acc[u][7]);
            *reinterpret_cast<float4*>(&Cm[ro])     = o0;
            *reinterpret_cast<float4*>(&Cm[ro + 4]) = o1;
        }
    })
}

// Symmetric distance kernel: only upper-triangular block pairs; mirror tile.
// D[i,j] = 2*<x_i,x_j> - xx_i - xx_j ; grid (NPAIR, 1, BB)
__global__ __launch_bounds__(256, 2)
void k_dist_sym(const float* __restrict__ X, int ld, int K) {
    int b = blockIdx.z;
    // map linear pair index -> (bi, bj), bi <= bj
    int t = blockIdx.x;
    int bi = 0;
    while (t >= (NTILE - bi)) { t -= (NTILE - bi); bi++; }
    int bj = bi + t;
    int bm = bi * 128, bn = bj * 128;
    const float* A = X + (size_t)b * NPTS * ld;
    const float* B = A;
    int lda = ld, ldb = ld;
    const float* xxb = g_xx + b * NPTS;
    float* Db = g_dist + (size_t)b * NPTS * NPTS;
    GEMM_CORE({
        float xj[8];
        *(float4*)&xj[0] = *(const float4*)&xxb[bn + tx * 8];
        *(float4*)&xj[4] = *(const float4*)&xxb[bn + tx * 8 + 4];
#pragma unroll
        for (int u = 0; u < 8; u++) {
            float xi = xxb[bm + ty * 8 + u];
#pragma unroll
            for (int v = 0; v < 8; v++)
                acc[u][v] = 2.f * acc[u][v] - xi - xj[v];
        }
        // direct tile
#pragma unroll
        for (int u = 0; u < 8; u++) {
            size_t ro = (size_t)(bm + ty * 8 + u) * NPTS + bn + tx * 8;
            *reinterpret_cast<float4*>(&Db[ro])     = make_float4(acc[u][0], acc[u][1], acc[u][2], acc[u][3]);
            *reinterpret_cast<float4*>(&Db[ro + 4]) = make_float4(acc[u][4], acc[u][5], acc[u][6], acc[u][7]);
        }
        // mirrored tile (transpose), skip on diagonal
        if (bi != bj) {
#pragma unroll
            for (int v = 0; v < 8; v++) {
                size_t ro = (size_t)(bn + tx * 8 + v) * NPTS + bm + ty * 8;
                *reinterpret_cast<float4*>(&Db[ro])     = make_float4(acc[0][v], acc[1][v], acc[2][v], acc[3][v]);
                *reinterpret_cast<float4*>(&Db[ro + 4]) = make_float4(acc[4][v], acc[5][v], acc[6][v], acc[7][v]);
            }
        }
    })
}

// warp per row: top-20 (set semantics only)
__global__ void k_topk() {
    int gw   = (blockIdx.x * blockDim.x + threadIdx.x) >> 5;
    int lane = threadIdx.x & 31;
    if (gw >= BN) return;
    const float* row = g_dist + (size_t)gw * NPTS;

    float v[KNN]; int id[KNN];
#pragma unroll
    for (int t = 0; t < KNN; t++) { v[t] = -FLT_MAX; id[t] = -1; }

    for (int j = lane; j < NPTS; j += 32) {
        float d = row[j];
        if (d > v[KNN - 1]) {
            int pos = KNN - 1;
            while (pos > 0 && v[pos - 1] < d) {
                v[pos] = v[pos - 1]; id[pos] = id[pos - 1]; pos--;
            }
            v[pos] = d; id[pos] = j;
        }
    }
    int p = 0;
    for (int t = 0; t < KNN; t++) {
        float bh = (p < KNN) ? v[p] : -FLT_MAX;
        int   bl = lane;
        for (int off = 16; off > 0; off >>= 1) {
            float oh = __shfl_down_sync(0xffffffffu, bh, off);
            int   ol = __shfl_down_sync(0xffffffffu, bl, off);
            if (oh > bh) { bh = oh; bl = ol; }
        }
        bl = __shfl_sync(0xffffffffu, bl, 0);
        int hid  = (p < KNN) ? id[p] : -1;
        int widx = __shfl_sync(0xffffffffu, hid, bl);
        if (lane == 0) g_idx[gw * KNN + t] = widx;
        if (lane == bl) p++;
    }
}

// wt[co] = W_d ; wt[Cout+co] = W_c - W_d
__global__ void k_transform_w(const float* __restrict__ w, float* __restrict__ wt,
                              int Cout, int Cin) {
    int i = blockIdx.x * blockDim.x + threadIdx.x;
    if (i >= Cout * Cin) return;
    int co = i / Cin, ci = i % Cin;
    float wd = w[co * 2 * Cin + ci];
    float wc = w[co * 2 * Cin + Cin + ci];
    wt[co * Cin + ci] = wd;
    wt[(Cout + co) * Cin + ci] = wc - wd;
}

// PPB points per block; thread co loops points; one atomic per thread per array
__global__ void k_edge_pool(const float* __restrict__ AC, int Cout) {
    int p0 = blockIdx.x * PPB;           // first global point index
    int b  = p0 / NPTS;                  // PPB divides NPTS -> single batch
    const float* ACb = AC + (size_t)b * NPTS * 2 * Cout;
    __shared__ int sidx[PPB * KNN];
    for (int i = threadIdx.x; i < PPB * KNN; i += blockDim.x)
        sidx[i] = g_idx[p0 * KNN + i];
    __syncthreads();
    int co = threadIdx.x;                // blockDim == Cout
    float s = 0.f, s2 = 0.f;
    for (int p = 0; p < PPB; p++) {
        int bn = p0 + p;
        float cc = AC[(size_t)bn * 2 * Cout + Cout + co];
        float vmax = -FLT_MAX, vmin = FLT_MAX;
#pragma unroll
        for (int kk = 0; kk < KNN; kk++) {
            float y = ACb[(size_t)sidx[p * KNN + kk] * 2 * Cout + co] + cc;
            vmax = fmaxf(vmax, y); vmin = fminf(vmin, y);
            s += y; s2 += y * y;
        }
        g_mx[(size_t)bn * Cout + co] = vmax;
        g_mn[(size_t)bn * Cout + co] = vmin;
    }
    atomicAdd(&g_sum[co], (double)s);
    atomicAdd(&g_sq[co], (double)s2);
}

// finalize into g_cat slice (row stride ldo)
__global__ void k_edge_fin(const float* __restrict__ gamma, const float* __restrict__ beta,
                           float* __restrict__ Xout, int ldo, int Cout) {
    int i = blockIdx.x * blockDim.x + threadIdx.x;
    if (i >= BN * Cout) return;
    int co = i % Cout, n = i / Cout;
    double cnt  = (double)BN * (double)KNN;
    double mean = g_sum[co] / cnt;
    double var  = g_sq[co] / cnt - mean * mean;
    float sc    = gamma[co] * rsqrtf((float)var + EPSBN);
    float m     = (sc >= 0.f) ? g_mx[i] : g_mn[i];
    float v     = (m - (float)mean) * sc + beta[co];
    Xout[(size_t)n * ldo + co] = (v > 0.f) ? v : SLOPE * v;
}

__global__ void k_pool5_partial() {
    int b = blockIdx.y, chunk = blockIdx.x;   // 16 chunks of 128 rows
    int c = threadIdx.x;                      // 512 threads
    float mx = -FLT_MAX, mn = FLT_MAX, s = 0.f, s2 = 0.f;
    int r0 = chunk * 128;
    for (int r = r0; r < r0 + 128; r++) {
        float v = g_y[((size_t)b * NPTS + r) * 512 + c];
        mx = fmaxf(mx, v); mn = fminf(mn, v);
        s += v; s2 += v * v;
    }
    g_p5max[(b * 16 + chunk) * 512 + c] = mx;
    g_p5min[(b * 16 + chunk) * 512 + c] = mn;
    atomicAdd(&g_sum[c], (double)s);
    atomicAdd(&g_sq[c], (double)s2);
}

__global__ void k_pool5_fin(const float* __restrict__ gamma, const float* __restrict__ beta) {
    int b = blockIdx.x, c = threadIdx.x;
    double cnt  = (double)BN;
    double mean = g_sum[c] / cnt;
    double var  = g_sq[c] / cnt - mean * mean;
    float sc    = gamma[c] * rsqrtf((float)var + EPSBN);
    float mx = -FLT_MAX, mn = FLT_MAX;
    for (int t = 0; t < 16; t++) {
        mx = fmaxf(mx, g_p5max[(b * 16 + t) * 512 + c]);
        mn = fminf(mn, g_p5min[(b * 16 + t) * 512 + c]);
    }
    float m = (sc >= 0.f) ? mx : mn;
    float v = (m - (float)mean) * sc + beta[c];
    g_z[b * 512 + c] = (v > 0.f) ? v : SLOPE * v;
}

__global__ void k_embed(const float* __restrict__ we, float* __restrict__ out) {
    int b = blockIdx.x, f = threadIdx.x;      // 128 threads
    const float* z  = g_z + b * 512;
    const float* wr = we + f * 512;
    float s = 0.f;
    for (int c = 0; c < 512; c++) s += z[c] * wr[c];
    out[b * 128 + f] = s;
}

// ---------------- host ----------------

static void edge_tail(const float* Xin, int ldx, int Cin,
                      const float* gamma, const float* beta,
                      int Cout, float* Xout, int ldo, float* wt, float* ac) {
    k_gemm128<<<dim3(2 * Cout / 128, BN / 128), 256>>>(Xin, ldx, wt, Cin,
                                                       ac, 2 * Cout, Cin);
    k_zero_sums<<<1, 512>>>();
    k_edge_pool<<<BN / PPB, Cout>>>(ac, Cout);
    k_edge_fin<<<(BN * Cout + 255) / 256, 256>>>(gamma, beta, Xout, ldo, Cout);
}

extern "C" void kernel_launch(void* const* d_in, const int* in_sizes, int n_in,
                              void* d_out, int out_size) {
    const float* x  = (const float*)d_in[0];
    const float* w1 = (const float*)d_in[1];
    const float* g1 = (const float*)d_in[2];
    const float* b1 = (const float*)d_in[3];
    const float* w2 = (const float*)d_in[4];
    const float* g2 = (const float*)d_in[5];
    const float* b2 = (const float*)d_in[6];
    const float* w3 = (const float*)d_in[7];
    const float* g3 = (const float*)d_in[8];
    const float* b3 = (const float*)d_in[9];
    const float* w4 = (const float*)d_in[10];
    const float* g4 = (const float*)d_in[11];
    const float* b4 = (const float*)d_in[12];
    const float* w5 = (const float*)d_in[13];
    const float* g5 = (const float*)d_in[14];
    const float* b5 = (const float*)d_in[15];
    const float* we = (const float*)d_in[16];
    float* out = (float*)d_out;

    void *p_cat, *p_ac, *p_y, *p_wt;
    cudaGetSymbolAddress(&p_cat, g_cat);
    cudaGetSymbolAddress(&p_ac, g_ac);
    cudaGetSymbolAddress(&p_y, g_y);
    cudaGetSymbolAddress(&p_wt, g_wt);
    float* cat = (float*)p_cat;
    float* ac  = (float*)p_ac;
    float* wt0 = (float*)p_wt;                 // 4 slices of 512*128
    float* wt1 = wt0 + 512 * 128;
    float* wt2 = wt1 + 512 * 128;
    float* wt3 = wt2 + 512 * 128;

    dim3 dsym(NPAIR, 1, BB);

    // ---- layer 1 (launch order puts k_dist_sym at index 3 for profiling) ----
    k_sqnorm<<<BN / 256, 256>>>(x, 3, 3);                       // 0
    k_transform_w<<<1, 256>>>(w1, wt0, 64, 3);                  // 1 (192 elems)
    k_transform_w<<<(64 * 64 + 255) / 256, 256>>>(w2, wt1, 64, 64);   // 2
    k_dist_sym<<<dsym, 256>>>(x, 3, 3);                         // 3 <- profiled
    k_transform_w<<<(128 * 64 + 255) / 256, 256>>>(w3, wt2, 128, 64); // 4
    k_transform_w<<<(256 * 128 + 255) / 256, 256>>>(w4, wt3, 256, 128); // 5
    k_topk<<<BN / 4, 128>>>();                                  // 6
    edge_tail(x, 3, 3, g1, b1, 64, cat + 0, 512, wt0, ac);

    // ---- layer 2 ----
    k_sqnorm<<<BN / 256, 256>>>(cat + 0, 512, 64);
    k_dist_sym<<<dsym, 256>>>(cat + 0, 512, 64);
    k_topk<<<BN / 4, 128>>>();
    edge_tail(cat + 0, 512, 64, g2, b2, 64, cat + 64, 512, wt1, ac);

    // ---- layer 3 ----
    k_sqnorm<<<BN / 256, 256>>>(cat + 64, 512, 64);
    k_dist_sym<<<dsym, 256>>>(cat + 64, 512, 64);
    k_topk<<<BN / 4, 128>>>();
    edge_tail(cat + 64, 512, 64, g3, b3, 128, cat + 128, 512, wt2, ac);

    // ---- layer 4 ----
    k_sqnorm<<<BN / 256, 256>>>(cat + 128, 512, 128);
    k_dist_sym<<<dsym, 256>>>(cat + 128, 512, 128);
    k_topk<<<BN / 4, 128>>>();
    edge_tail(cat + 128, 512, 128, g4, b4, 256, cat + 256, 512, wt3, ac);

    // ---- conv5 + pool + embed ----
    k_gemm128<<<dim3(512 / 128, BN / 128), 256>>>(cat, 512, w5, 512,
                                                  (float*)p_y, 512, 512);
    k_zero_sums<<<1, 512>>>();
    k_pool5_partial<<<dim3(16, BB), 512>>>();
    k_pool5_fin<<<BB, 512>>>(g5, b5);
    k_embed<<<BB, 128>>>(we, out);
}